// round 4
// baseline (speedup 1.0000x reference)
#include <cuda_runtime.h>
#include <math.h>

// Problem constants (fixed by the reference)
#define N_POS 4096   // spatial positions
#define C_CH  512    // channels
#define D_K   64     // key/query dim

// Scratch (device globals — no allocation allowed)
__device__ float g_kx[D_K * N_POS];            // [64][4096]  kx[d][i]
__device__ float g_qx[D_K * N_POS];            // [64][4096]  qx[d][j]
__device__ float g_vx[C_CH * N_POS];           // [512][4096] vx[c][j]
__device__ float g_S[(size_t)N_POS * N_POS];   // [4096][4096] scores -> probs (in place)
__device__ float g_m[N_POS];                   // row max
__device__ float g_l[N_POS];                   // row sum-exp

// ----------------------------------------------------------------------------
// Kernel 1: projections  C[M,N] = W[M,512] @ x[512,4096]
// 64x64 tile, K-tile 16, 256 threads, 4x4 microtile.
// sel: 0 -> g_kx (M=64), 1 -> g_qx (M=64), 2 -> g_vx (M=512)
// ----------------------------------------------------------------------------
__global__ __launch_bounds__(256) void proj_gemm_kernel(
    const float* __restrict__ W, const float* __restrict__ x, int sel)
{
    float* C = (sel == 0) ? g_kx : (sel == 1) ? g_qx : g_vx;

    __shared__ float a_sh[16][64];  // [k][m]
    __shared__ float b_sh[16][64];  // [k][n]

    const int t  = threadIdx.x;
    const int tx = t & 15;
    const int ty = t >> 4;
    const int n0 = blockIdx.x * 64;
    const int m0 = blockIdx.y * 64;

    float acc[4][4] = {};

    for (int k0 = 0; k0 < C_CH; k0 += 16) {
        {
            int m  = t >> 2;
            int kk = (t & 3) << 2;
            float4 av = *(const float4*)&W[(size_t)(m0 + m) * C_CH + k0 + kk];
            a_sh[kk + 0][m] = av.x;
            a_sh[kk + 1][m] = av.y;
            a_sh[kk + 2][m] = av.z;
            a_sh[kk + 3][m] = av.w;
        }
        {
            int kk = t >> 4;
            int n  = (t & 15) << 2;
            *(float4*)&b_sh[kk][n] =
                *(const float4*)&x[(size_t)(k0 + kk) * N_POS + n0 + n];
        }
        __syncthreads();

#pragma unroll
        for (int kk = 0; kk < 16; kk++) {
            float4 a4 = *(const float4*)&a_sh[kk][ty * 4];
            float4 b4 = *(const float4*)&b_sh[kk][tx * 4];
            float af[4] = {a4.x, a4.y, a4.z, a4.w};
            float bf[4] = {b4.x, b4.y, b4.z, b4.w};
#pragma unroll
            for (int u = 0; u < 4; u++)
#pragma unroll
                for (int v = 0; v < 4; v++)
                    acc[u][v] = fmaf(af[u], bf[v], acc[u][v]);
        }
        __syncthreads();
    }

#pragma unroll
    for (int u = 0; u < 4; u++) {
        float4 o = make_float4(acc[u][0], acc[u][1], acc[u][2], acc[u][3]);
        *(float4*)&C[(size_t)(m0 + ty * 4 + u) * N_POS + n0 + tx * 4] = o;
    }
}

// ----------------------------------------------------------------------------
// Kernel 2: scores  S[i][j] = sum_d kx[d][i] * qx[d][j]
// 64x64 tile, K=64 (single shot), 256 threads, 4x4 microtile.
// ----------------------------------------------------------------------------
__global__ __launch_bounds__(256) void score_gemm_kernel()
{
    __shared__ float a_sh[64][64];  // [d][i]
    __shared__ float b_sh[64][64];  // [d][j]

    const int t  = threadIdx.x;
    const int tx = t & 15;
    const int ty = t >> 4;
    const int j0 = blockIdx.x * 64;
    const int i0 = blockIdx.y * 64;

#pragma unroll
    for (int r = 0; r < 16; r++) {
        int idx = t + r * 256;
        int d = idx >> 6;
        int c = idx & 63;
        a_sh[d][c] = g_kx[(size_t)d * N_POS + i0 + c];
        b_sh[d][c] = g_qx[(size_t)d * N_POS + j0 + c];
    }
    __syncthreads();

    float acc[4][4] = {};
#pragma unroll
    for (int d = 0; d < 64; d++) {
        float4 a4 = *(const float4*)&a_sh[d][ty * 4];
        float4 b4 = *(const float4*)&b_sh[d][tx * 4];
        float af[4] = {a4.x, a4.y, a4.z, a4.w};
        float bf[4] = {b4.x, b4.y, b4.z, b4.w};
#pragma unroll
        for (int u = 0; u < 4; u++)
#pragma unroll
            for (int v = 0; v < 4; v++)
                acc[u][v] = fmaf(af[u], bf[v], acc[u][v]);
    }

#pragma unroll
    for (int u = 0; u < 4; u++) {
        float4 o = make_float4(acc[u][0], acc[u][1], acc[u][2], acc[u][3]);
        *(float4*)&g_S[(size_t)(i0 + ty * 4 + u) * N_POS + j0 + tx * 4] = o;
    }
}

// ----------------------------------------------------------------------------
// Kernel 3: full softmax, in place. One warp per row of g_S.
// pass1: row max; pass2: sum exp; pass3: overwrite S with exp(s-m)/l.
// S is L2-resident (64MB), so the extra passes are cheap.
// ----------------------------------------------------------------------------
__global__ __launch_bounds__(256) void softmax_kernel()
{
    const int warp = (blockIdx.x * blockDim.x + threadIdx.x) >> 5;
    const int lane = threadIdx.x & 31;
    if (warp >= N_POS) return;

    float* row = g_S + (size_t)warp * N_POS;

    float m = -INFINITY;
#pragma unroll 4
    for (int j = lane * 4; j < N_POS; j += 128) {
        float4 v = *(const float4*)&row[j];
        m = fmaxf(m, fmaxf(fmaxf(v.x, v.y), fmaxf(v.z, v.w)));
    }
#pragma unroll
    for (int o = 16; o; o >>= 1) m = fmaxf(m, __shfl_xor_sync(0xffffffffu, m, o));

    float l = 0.f;
#pragma unroll 4
    for (int j = lane * 4; j < N_POS; j += 128) {
        float4 v = *(const float4*)&row[j];
        l += __expf(v.x - m) + __expf(v.y - m) + __expf(v.z - m) + __expf(v.w - m);
    }
#pragma unroll
    for (int o = 16; o; o >>= 1) l += __shfl_xor_sync(0xffffffffu, l, o);

    const float linv = 1.0f / l;

#pragma unroll 4
    for (int j = lane * 4; j < N_POS; j += 128) {
        float4 v = *(const float4*)&row[j];
        v.x = __expf(v.x - m) * linv;
        v.y = __expf(v.y - m) * linv;
        v.z = __expf(v.z - m) * linv;
        v.w = __expf(v.w - m) * linv;
        *(float4*)&row[j] = v;
    }
}

// ----------------------------------------------------------------------------
// Kernel 4: out[i][c] = sum_j P[i][j] * vx[c][j]      (P = g_S, normalized)
// GEMM M=4096(i) x N=512(c), K=4096(j). 128x64 tile, K-tile 32,
// 256 threads, 8x4 microtile. grid: (8 c-blocks, 32 i-blocks)
//   a_sh: [i][kk] padded to 36 (STS.128 conflict-free, scalar broadcast reads)
//   b_sh: [kk][c]             (float4 conflict-free reads)
// ----------------------------------------------------------------------------
__global__ __launch_bounds__(256) void pv_gemm_kernel(float* __restrict__ out)
{
    __shared__ float a_sh[128][36];  // [i][kk]  (36*4=144B row: 16B aligned, bank-spread)
    __shared__ float b_sh[32][64];   // [kk][c]

    const int t  = threadIdx.x;
    const int tx = t & 15;   // c group: c = tx*4 + v
    const int ty = t >> 4;   // i group: i = ty*8 + u
    const int c0 = blockIdx.x * 64;
    const int i0 = blockIdx.y * 128;

    // staging coordinates
    const int ai = t >> 1;            // 0..127 (row of P tile)
    const int aj = (t & 1) * 16;      // 0 or 16 (64B chunk within k-tile)
    const int bc = t >> 2;            // 0..63  (row of V tile)
    const int bj = (t & 3) * 8;       // 0,8,16,24

    const float* arow = &g_S[(size_t)(i0 + ai) * N_POS + aj];
    const float* brow = &g_vx[(size_t)(c0 + bc) * N_POS + bj];

    float acc[8][4] = {};

    for (int k0 = 0; k0 < N_POS; k0 += 32) {
        // global loads first (overlap with previous tile's compute before sync)
        float4 p0 = *(const float4*)&arow[k0 + 0];
        float4 p1 = *(const float4*)&arow[k0 + 4];
        float4 p2 = *(const float4*)&arow[k0 + 8];
        float4 p3 = *(const float4*)&arow[k0 + 12];
        float4 v0 = *(const float4*)&brow[k0 + 0];
        float4 v1 = *(const float4*)&brow[k0 + 4];
        __syncthreads();   // previous iteration's compute done

        // P tile: contiguous float4 stores (conflict-free with 36-pad)
        *(float4*)&a_sh[ai][aj + 0]  = p0;
        *(float4*)&a_sh[ai][aj + 4]  = p1;
        *(float4*)&a_sh[ai][aj + 8]  = p2;
        *(float4*)&a_sh[ai][aj + 12] = p3;
        // V tile: transpose into [kk][c]
        b_sh[bj + 0][bc] = v0.x;
        b_sh[bj + 1][bc] = v0.y;
        b_sh[bj + 2][bc] = v0.z;
        b_sh[bj + 3][bc] = v0.w;
        b_sh[bj + 4][bc] = v1.x;
        b_sh[bj + 5][bc] = v1.y;
        b_sh[bj + 6][bc] = v1.z;
        b_sh[bj + 7][bc] = v1.w;
        __syncthreads();

#pragma unroll
        for (int kk = 0; kk < 32; kk++) {
            float4 b4 = *(const float4*)&b_sh[kk][tx * 4];
            float bf[4] = {b4.x, b4.y, b4.z, b4.w};
            float af[8];
#pragma unroll
            for (int u = 0; u < 8; u++) af[u] = a_sh[ty * 8 + u][kk];
#pragma unroll
            for (int u = 0; u < 8; u++)
#pragma unroll
                for (int v = 0; v < 4; v++)
                    acc[u][v] = fmaf(af[u], bf[v], acc[u][v]);
        }
    }

#pragma unroll
    for (int u = 0; u < 8; u++) {
        float4 o = make_float4(acc[u][0], acc[u][1], acc[u][2], acc[u][3]);
        *(float4*)&out[(size_t)(i0 + ty * 8 + u) * C_CH + c0 + tx * 4] = o;
    }
}

// ----------------------------------------------------------------------------
// Launch
// ----------------------------------------------------------------------------
extern "C" void kernel_launch(void* const* d_in, const int* in_sizes, int n_in,
                              void* d_out, int out_size)
{
    const float* x  = (const float*)d_in[0];  // [512, 4096]
    const float* Wk = (const float*)d_in[1];  // [64, 512]
    const float* Wq = (const float*)d_in[2];  // [64, 512]
    const float* Wv = (const float*)d_in[3];  // [512, 512]
    float* out = (float*)d_out;               // [4096, 512]

    // projections
    proj_gemm_kernel<<<dim3(64, 1), 256>>>(Wk, x, 0);
    proj_gemm_kernel<<<dim3(64, 1), 256>>>(Wq, x, 1);
    proj_gemm_kernel<<<dim3(64, 8), 256>>>(Wv, x, 2);

    // scores S = kx^T qx
    score_gemm_kernel<<<dim3(64, 64), 256>>>();

    // full softmax in place (S -> P)
    softmax_kernel<<<512, 256>>>();

    // out = P @ vx^T
    pv_gemm_kernel<<<dim3(8, 32), 256>>>(out);
}